// round 2
// baseline (speedup 1.0000x reference)
#include <cuda_runtime.h>
#include <cuda_bf16.h>
#include <cstddef>

// ---------------- problem constants ----------------
// x:    [4, 8, 32, 32, 128]
// w1:   [4, 3,3,3, 128, 64]
// w2:   [4, 3,3,3, 128, 64]
// skip: [4, 16, 64, 64, 64]
// out:  [4, 16, 64, 64, 64]
#define B     4
#define Dc    8
#define Hc    32
#define Wc_   32
#define Cin   128
#define Cmid  64
#define Df    16
#define Hf    64
#define Wf    64
#define NPOS  (B*Df*Hf*Wf)        // 262,144 positions (per-channel BN count)
#define BN_EPS 1e-3f

#define STATS_BLOCKS 512

// ---------------- device scratch ----------------
__device__ float g_y1[B*Df*Hf*Wf*Cmid];          // 16.78M floats: raw conv1 output
__device__ float g_wcomb[B*8*8*Cin*Cmid];        // folded conv1 weights [b][parity][tap][ci][co]
__device__ float g_part[STATS_BLOCKS*128];       // per-block partial (sum, sumsq)
__device__ float g_ss1[128];                     // scale[64], shift[64] for BN1
__device__ float g_ss2[128];                     // scale[64], shift[64] for BN2

// For parity p, tap t (each in {0,1}):
//   p=0: coarse offsets {-1, 0}, weights {w0, w1+w2}
//   p=1: coarse offsets { 0,+1}, weights {w0+w1, w2}
__device__ __forceinline__ bool tap_in_set(int p, int t, int k) {
    return p ? (t ? (k == 2) : (k <= 1)) : (t ? (k >= 1) : (k == 0));
}

// ---------------- build folded conv1 weights ----------------
__global__ void build_wcomb(const float* __restrict__ w1) {
    int idx = blockIdx.x * 256 + threadIdx.x;     // exactly 4*8*8*128*64 = 2,097,152
    int co  = idx & 63;
    int ci  = (idx >> 6) & 127;
    int tap = (idx >> 13) & 7;
    int par = (idx >> 16) & 7;
    int b   = idx >> 19;
    int td = (tap >> 2) & 1, th = (tap >> 1) & 1, tw = tap & 1;
    int pd = (par >> 2) & 1, ph = (par >> 1) & 1, pw = par & 1;
    float s = 0.f;
    #pragma unroll
    for (int kd = 0; kd < 3; ++kd) {
        if (!tap_in_set(pd, td, kd)) continue;
        #pragma unroll
        for (int kh = 0; kh < 3; ++kh) {
            if (!tap_in_set(ph, th, kh)) continue;
            #pragma unroll
            for (int kw = 0; kw < 3; ++kw) {
                if (!tap_in_set(pw, tw, kw)) continue;
                s += w1[((((b*3+kd)*3+kh)*3+kw)*Cin + ci)*Cmid + co];
            }
        }
    }
    g_wcomb[idx] = s;
}

// ---------------- conv1: folded 2x2x2 conv on coarse grid ----------------
// GEMM per (batch, parity): M = 8*32*32 = 8192 coarse positions, N = 64, K = 8 taps * 128 ci.
// Tile: 128(M) x 64(N), 256 threads, 8x4 per-thread fragment, double-buffered.
__global__ void __launch_bounds__(256) conv1_kernel(const float* __restrict__ x) {
    const int b   = blockIdx.z;
    const int par = blockIdx.y;
    const int pd = (par >> 2) & 1, ph = (par >> 1) & 1, pw = par & 1;
    const int t  = threadIdx.x;
    const int tm = t & 15, tn = t >> 4;

    __shared__ __align__(16) float As[2][8][132];   // padded to kill STS bank conflicts
    __shared__ __align__(16) float Bs[2][8][64];

    const int lm = t >> 1;            // 0..127 (M row this thread loads)
    const int lc = (t & 1) * 4;       // ci sub-offset within 8-chunk
    const int m  = blockIdx.x * 128 + lm;
    const int mw = m & 31, mh = (m >> 5) & 31, md = m >> 10;

    const float* wptr = g_wcomb + (size_t)((b*8 + par) * 8) * (Cin*Cmid) + t*2;

    float acc[8][4];
    #pragma unroll
    for (int i = 0; i < 8; ++i)
        #pragma unroll
        for (int j = 0; j < 4; ++j) acc[i][j] = 0.f;

    const float* aBase = x;
    int aValid = 0;

#define C1_SET_TAP(TAP) { \
    int td_ = ((TAP) >> 2) & 1, th_ = ((TAP) >> 1) & 1, tw_ = (TAP) & 1; \
    int z_ = md + (pd ? td_ : td_ - 1); \
    int y_ = mh + (ph ? th_ : th_ - 1); \
    int x_ = mw + (pw ? tw_ : tw_ - 1); \
    aValid = ((unsigned)z_ < (unsigned)Dc) & ((unsigned)y_ < (unsigned)Hc) & ((unsigned)x_ < (unsigned)Wc_); \
    aBase  = x + ((size_t)(((b*Dc + z_)*Hc + y_)*Wc_ + x_))*Cin + lc; \
}

    float4 aReg; float2 bReg;
    C1_SET_TAP(0);
    aReg = aValid ? *(const float4*)(aBase) : make_float4(0.f,0.f,0.f,0.f);
    bReg = *(const float2*)(wptr);

    // prime buffer 0
    As[0][lc+0][lm] = aReg.x; As[0][lc+1][lm] = aReg.y;
    As[0][lc+2][lm] = aReg.z; As[0][lc+3][lm] = aReg.w;
    ((float2*)&Bs[0][0][0])[t] = bReg;

    const int KIT = 128;   // 8 taps * 16 ci-chunks
    for (int it = 0; it < KIT; ++it) {
        __syncthreads();
        const int nit = it + 1;
        if (nit < KIT) {
            const int ncc = nit & 15;
            if (ncc == 0) { C1_SET_TAP(nit >> 4); }
            aReg = aValid ? *(const float4*)(aBase + ncc*8) : make_float4(0.f,0.f,0.f,0.f);
            bReg = *(const float2*)(wptr + (size_t)nit*512);
        }
        const int buf = it & 1;
        #pragma unroll
        for (int k = 0; k < 8; ++k) {
            float4 a0 = *(const float4*)&As[buf][k][tm*4];
            float4 a1 = *(const float4*)&As[buf][k][64 + tm*4];
            float4 b4 = *(const float4*)&Bs[buf][k][tn*4];
            float av[8] = {a0.x,a0.y,a0.z,a0.w,a1.x,a1.y,a1.z,a1.w};
            float bv[4] = {b4.x,b4.y,b4.z,b4.w};
            #pragma unroll
            for (int i = 0; i < 8; ++i)
                #pragma unroll
                for (int j = 0; j < 4; ++j)
                    acc[i][j] = fmaf(av[i], bv[j], acc[i][j]);
        }
        if (nit < KIT) {
            const int nb = nit & 1;
            As[nb][lc+0][lm] = aReg.x; As[nb][lc+1][lm] = aReg.y;
            As[nb][lc+2][lm] = aReg.z; As[nb][lc+3][lm] = aReg.w;
            ((float2*)&Bs[nb][0][0])[t] = bReg;
        }
    }
#undef C1_SET_TAP

    // write raw conv1 output to g_y1 at fine coordinates
    #pragma unroll
    for (int i = 0; i < 8; ++i) {
        int mrow = blockIdx.x*128 + ((i < 4) ? (tm*4 + i) : (64 + tm*4 + (i - 4)));
        int ww = mrow & 31, hh = (mrow >> 5) & 31, dd = mrow >> 10;
        int od = 2*dd + pd, oh = 2*hh + ph, ow = 2*ww + pw;
        float4 v = make_float4(acc[i][0], acc[i][1], acc[i][2], acc[i][3]);
        *(float4*)(g_y1 + ((size_t)(((b*Df + od)*Hf + oh)*Wf + ow))*Cmid + tn*4) = v;
    }
}

// ---------------- conv2: full 3x3x3 over concat(BN1+ReLU(y1), skip) ----------------
// GEMM per batch: M = 16*64*64 = 65536, N = 64, K = 27 taps * 128 ci.
__global__ void __launch_bounds__(256) conv2_kernel(const float* __restrict__ skip,
                                                    const float* __restrict__ w2,
                                                    float* __restrict__ out) {
    const int b = blockIdx.y;
    const int t = threadIdx.x;
    const int tm = t & 15, tn = t >> 4;

    __shared__ __align__(16) float As[2][8][132];
    __shared__ __align__(16) float Bs[2][8][64];
    __shared__ __align__(16) float sS[64], sH[64];

    if (t < 64)       sS[t]      = g_ss1[t];
    else if (t < 128) sH[t - 64] = g_ss1[t];
    __syncthreads();

    const int lm = t >> 1;
    const int lc = (t & 1) * 4;
    const int m  = blockIdx.x * 128 + lm;
    const int ow_ = m & 63, oh_ = (m >> 6) & 63, od_ = m >> 12;

    const float* wptr = w2 + (size_t)b * 27 * (128*Cmid) + t*2;

    float acc[8][4];
    #pragma unroll
    for (int i = 0; i < 8; ++i)
        #pragma unroll
        for (int j = 0; j < 4; ++j) acc[i][j] = 0.f;

    const float* y1Base = g_y1;   // lc-FREE base (bug fix: lc was added twice before)
    const float* skBase = skip;   // lc-FREE base
    int aValid = 0;

#define C2_SET_TAP(TAP) { \
    int td_ = (TAP)/9, r_ = (TAP)%9; int th_ = r_/3, tw_ = r_%3; \
    int z_ = od_ + td_ - 1, y_ = oh_ + th_ - 1, x_ = ow_ + tw_ - 1; \
    aValid = ((unsigned)z_ < (unsigned)Df) & ((unsigned)y_ < (unsigned)Hf) & ((unsigned)x_ < (unsigned)Wf); \
    size_t sp_ = ((size_t)(((b*Df + z_)*Hf + y_)*Wf + x_))*Cmid; \
    y1Base = g_y1 + sp_; skBase = skip + sp_; \
}

#define C2_FETCH(CC, DST) { \
    if (aValid) { \
        int ci_ = (CC)*8 + lc; \
        if (ci_ < 64) { \
            float4 v_ = *(const float4*)(y1Base + ci_); \
            float4 s_ = *(const float4*)&sS[ci_]; \
            float4 h_ = *(const float4*)&sH[ci_]; \
            DST.x = fmaxf(fmaf(v_.x, s_.x, h_.x), 0.f); \
            DST.y = fmaxf(fmaf(v_.y, s_.y, h_.y), 0.f); \
            DST.z = fmaxf(fmaf(v_.z, s_.z, h_.z), 0.f); \
            DST.w = fmaxf(fmaf(v_.w, s_.w, h_.w), 0.f); \
        } else { \
            DST = *(const float4*)(skBase + (ci_ - 64)); \
        } \
    } else { DST = make_float4(0.f,0.f,0.f,0.f); } \
}

    float4 aReg; float2 bReg;
    C2_SET_TAP(0);
    C2_FETCH(0, aReg);
    bReg = *(const float2*)(wptr);

    As[0][lc+0][lm] = aReg.x; As[0][lc+1][lm] = aReg.y;
    As[0][lc+2][lm] = aReg.z; As[0][lc+3][lm] = aReg.w;
    ((float2*)&Bs[0][0][0])[t] = bReg;

    const int KIT = 27 * 16;   // 432
    for (int it = 0; it < KIT; ++it) {
        __syncthreads();
        const int nit = it + 1;
        if (nit < KIT) {
            const int ncc = nit & 15;
            if (ncc == 0) { C2_SET_TAP(nit >> 4); }
            C2_FETCH(ncc, aReg);
            bReg = *(const float2*)(wptr + (size_t)nit*512);
        }
        const int buf = it & 1;
        #pragma unroll
        for (int k = 0; k < 8; ++k) {
            float4 a0 = *(const float4*)&As[buf][k][tm*4];
            float4 a1 = *(const float4*)&As[buf][k][64 + tm*4];
            float4 b4 = *(const float4*)&Bs[buf][k][tn*4];
            float av[8] = {a0.x,a0.y,a0.z,a0.w,a1.x,a1.y,a1.z,a1.w};
            float bv[4] = {b4.x,b4.y,b4.z,b4.w};
            #pragma unroll
            for (int i = 0; i < 8; ++i)
                #pragma unroll
                for (int j = 0; j < 4; ++j)
                    acc[i][j] = fmaf(av[i], bv[j], acc[i][j]);
        }
        if (nit < KIT) {
            const int nb = nit & 1;
            As[nb][lc+0][lm] = aReg.x; As[nb][lc+1][lm] = aReg.y;
            As[nb][lc+2][lm] = aReg.z; As[nb][lc+3][lm] = aReg.w;
            ((float2*)&Bs[nb][0][0])[t] = bReg;
        }
    }
#undef C2_SET_TAP
#undef C2_FETCH

    #pragma unroll
    for (int i = 0; i < 8; ++i) {
        int mrow = blockIdx.x*128 + ((i < 4) ? (tm*4 + i) : (64 + tm*4 + (i - 4)));
        float4 v = make_float4(acc[i][0], acc[i][1], acc[i][2], acc[i][3]);
        *(float4*)(out + ((size_t)b*(Df*Hf*Wf) + mrow)*Cmid + tn*4) = v;
    }
}

// ---------------- BN statistics (deterministic two-stage) ----------------
__global__ void stats_partial(const float* __restrict__ extsrc, int use_y1) {
    const float* src = use_y1 ? g_y1 : extsrc;
    const int c = threadIdx.x & 63;
    const int r = threadIdx.x >> 6;   // 0..3
    float s = 0.f, q = 0.f;
    for (int p = blockIdx.x*4 + r; p < NPOS; p += STATS_BLOCKS*4) {
        float v = src[(size_t)p*64 + c];
        s += v; q = fmaf(v, v, q);
    }
    __shared__ float shs[4][64], shq[4][64];
    shs[r][c] = s; shq[r][c] = q;
    __syncthreads();
    if (r == 0) {
        s = shs[0][c] + shs[1][c] + shs[2][c] + shs[3][c];
        q = shq[0][c] + shq[1][c] + shq[2][c] + shq[3][c];
        g_part[blockIdx.x*128 + c]      = s;
        g_part[blockIdx.x*128 + 64 + c] = q;
    }
}

__global__ void reduce_stats(const float* __restrict__ gamma,
                             const float* __restrict__ beta,
                             int which) {   // 1 -> g_ss1, 0 -> g_ss2
    int c = threadIdx.x;   // 0..63
    float s = 0.f, q = 0.f;
    for (int i = 0; i < STATS_BLOCKS; ++i) {
        s += g_part[i*128 + c];
        q += g_part[i*128 + 64 + c];
    }
    float mean = s * (1.f / (float)NPOS);
    float var  = q * (1.f / (float)NPOS) - mean*mean;
    float sc   = gamma[c] * rsqrtf(var + BN_EPS);
    float sh   = beta[c] - mean * sc;
    float* ss = which ? g_ss1 : g_ss2;
    ss[c]      = sc;
    ss[64 + c] = sh;
}

// ---------------- final BN2 + ReLU, in place on d_out ----------------
__global__ void bn_relu_kernel(float* __restrict__ out) {
    __shared__ float s[128];
    if (threadIdx.x < 128) s[threadIdx.x] = g_ss2[threadIdx.x];
    __syncthreads();
    size_t i = (size_t)blockIdx.x*256 + threadIdx.x;     // exactly 16,777,216/4 float4s
    float4 v = ((float4*)out)[i];
    int cb = ((int)i & 15) * 4;
    v.x = fmaxf(fmaf(v.x, s[cb+0], s[64+cb+0]), 0.f);
    v.y = fmaxf(fmaf(v.y, s[cb+1], s[64+cb+1]), 0.f);
    v.z = fmaxf(fmaf(v.z, s[cb+2], s[64+cb+2]), 0.f);
    v.w = fmaxf(fmaf(v.w, s[cb+3], s[64+cb+3]), 0.f);
    ((float4*)out)[i] = v;
}

// ---------------- launcher ----------------
extern "C" void kernel_launch(void* const* d_in, const int* in_sizes, int n_in,
                              void* d_out, int out_size) {
    (void)in_sizes; (void)n_in; (void)out_size;
    const float* x      = (const float*)d_in[0];
    const float* w1     = (const float*)d_in[1];
    const float* w2     = (const float*)d_in[2];
    const float* skip   = (const float*)d_in[3];
    const float* gamma1 = (const float*)d_in[4];
    const float* beta1  = (const float*)d_in[5];
    const float* gamma2 = (const float*)d_in[6];
    const float* beta2  = (const float*)d_in[7];
    float* out = (float*)d_out;

    // 1) fold conv1 weights per (batch, parity)
    build_wcomb<<<8192, 256>>>(w1);
    // 2) conv1 (raw) -> g_y1
    conv1_kernel<<<dim3(64, 8, B), 256>>>(x);
    // 3) BN1 stats
    stats_partial<<<STATS_BLOCKS, 256>>>(nullptr, 1);
    reduce_stats<<<1, 64>>>(gamma1, beta1, 1);
    // 4) conv2 (applies BN1+ReLU on the fly, concat via channel split) -> out (raw)
    conv2_kernel<<<dim3(512, B), 256>>>(skip, w2, out);
    // 5) BN2 stats
    stats_partial<<<STATS_BLOCKS, 256>>>(out, 0);
    reduce_stats<<<1, 64>>>(gamma2, beta2, 0);
    // 6) BN2 + ReLU in place
    bn_relu_kernel<<<16384, 256>>>(out);
}

// round 4
// speedup vs baseline: 2.2420x; 2.2420x over previous
#include <cuda_runtime.h>
#include <cuda_bf16.h>
#include <cstdint>
#include <cstddef>

// ---------------- problem constants ----------------
#define B     4
#define Dc    8
#define Hc    32
#define Wc_   32
#define Cin   128
#define Cmid  64
#define Df    16
#define Hf    64
#define Wf    64
#define NPOS  (B*Df*Hf*Wf)
#define BN_EPS 1e-3f
#define STATS_BLOCKS 512

// ---------------- device scratch ----------------
__device__ float g_y1[(size_t)NPOS*Cmid];              // raw conv1 output (fp32, for BN1 stats)
__device__ float g_wcomb[B*8*8*Cin*Cmid];              // folded conv1 weights (fp32)
__device__ float g_part[STATS_BLOCKS*128];
__device__ float g_ss1[128];                           // BN1 scale[64],shift[64]
__device__ float g_ss2[128];

__device__ __align__(16) __nv_bfloat16 g_xh[B*Dc*Hc*Wc_*Cin];
__device__ __align__(16) __nv_bfloat16 g_xl[B*Dc*Hc*Wc_*Cin];
__device__ __align__(16) __nv_bfloat16 g_skh[(size_t)NPOS*Cmid];
__device__ __align__(16) __nv_bfloat16 g_skl[(size_t)NPOS*Cmid];
__device__ __align__(16) __nv_bfloat16 g_y1h[(size_t)NPOS*Cmid];
__device__ __align__(16) __nv_bfloat16 g_y1l[(size_t)NPOS*Cmid];
__device__ __align__(16) __nv_bfloat16 g_B1h[B*8*Cmid*1024];   // [b][par][co][k=tap*128+ci]
__device__ __align__(16) __nv_bfloat16 g_B1l[B*8*Cmid*1024];
__device__ __align__(16) __nv_bfloat16 g_B2h[B*Cmid*3456];     // [b][co][k=tap*128+ci]
__device__ __align__(16) __nv_bfloat16 g_B2l[B*Cmid*3456];

// ---------------- warp-MMA helpers (baseline PTX, compiles for plain sm_103) ----------
__device__ __forceinline__ uint32_t smem_u32(const void* p) {
    uint32_t a;
    asm("{ .reg .u64 t; cvta.to.shared.u64 t, %1; cvt.u32.u64 %0, t; }" : "=r"(a) : "l"(p));
    return a;
}
__device__ __forceinline__ void ldsm4(uint32_t* r, uint32_t addr) {
    asm volatile("ldmatrix.sync.aligned.m8n8.x4.shared.b16 {%0,%1,%2,%3}, [%4];"
                 : "=r"(r[0]), "=r"(r[1]), "=r"(r[2]), "=r"(r[3]) : "r"(addr));
}
__device__ __forceinline__ void ldsm2(uint32_t* r, uint32_t addr) {
    asm volatile("ldmatrix.sync.aligned.m8n8.x2.shared.b16 {%0,%1}, [%2];"
                 : "=r"(r[0]), "=r"(r[1]) : "r"(addr));
}
__device__ __forceinline__ void mma16816(float* c, const uint32_t* a, const uint32_t* b) {
    asm volatile("mma.sync.aligned.m16n8k16.row.col.f32.bf16.bf16.f32 "
                 "{%0,%1,%2,%3}, {%4,%5,%6,%7}, {%8,%9}, {%0,%1,%2,%3};"
                 : "+f"(c[0]), "+f"(c[1]), "+f"(c[2]), "+f"(c[3])
                 : "r"(a[0]), "r"(a[1]), "r"(a[2]), "r"(a[3]), "r"(b[0]), "r"(b[1]));
}
__device__ __forceinline__ void sts16(uint32_t addr, uint4 v) {
    asm volatile("st.shared.v4.b32 [%0], {%1,%2,%3,%4};"
                 :: "r"(addr), "r"(v.x), "r"(v.y), "r"(v.z), "r"(v.w) : "memory");
}

// ---------------- SMEM layout (byte offsets; A stride 72 bf16 = 144B, conflict-free ldmatrix)
#define APITCH 72
#define SA_H(bf) ((bf)*55296u + 0u)        // 128 x 72 bf16 = 18432 B
#define SA_L(bf) ((bf)*55296u + 18432u)
#define SB_H(bf) ((bf)*55296u + 36864u)    // 64 x 72 bf16 = 9216 B
#define SB_L(bf) ((bf)*55296u + 46080u)
#define SMEM_DYN 110592

// ---------------- fp32 -> bf16 hi/lo split helpers ----------------
__device__ __forceinline__ void split1(float v, uint16_t& h, uint16_t& l) {
    __nv_bfloat16 hb = __float2bfloat16(v);
    __nv_bfloat16 lb = __float2bfloat16(v - __bfloat162float(hb));
    h = __bfloat16_as_ushort(hb); l = __bfloat16_as_ushort(lb);
}
__device__ __forceinline__ void split4(float4 v, uint2& H, uint2& L) {
    uint16_t h0,h1,h2,h3,l0,l1,l2,l3;
    split1(v.x,h0,l0); split1(v.y,h1,l1); split1(v.z,h2,l2); split1(v.w,h3,l3);
    H.x = (uint32_t)h0 | ((uint32_t)h1 << 16); H.y = (uint32_t)h2 | ((uint32_t)h3 << 16);
    L.x = (uint32_t)l0 | ((uint32_t)l1 << 16); L.y = (uint32_t)l2 | ((uint32_t)l3 << 16);
}

// ---------------- conv1 weight folding ----------------
__device__ __forceinline__ bool tap_in_set(int p, int t, int k) {
    return p ? (t ? (k == 2) : (k <= 1)) : (t ? (k >= 1) : (k == 0));
}
__global__ void build_wcomb(const float* __restrict__ w1) {
    int idx = blockIdx.x * 256 + threadIdx.x;
    int co  = idx & 63;
    int ci  = (idx >> 6) & 127;
    int tap = (idx >> 13) & 7;
    int par = (idx >> 16) & 7;
    int b   = idx >> 19;
    int td = (tap >> 2) & 1, th = (tap >> 1) & 1, tw = tap & 1;
    int pd = (par >> 2) & 1, ph = (par >> 1) & 1, pw = par & 1;
    float s = 0.f;
    #pragma unroll
    for (int kd = 0; kd < 3; ++kd) { if (!tap_in_set(pd, td, kd)) continue;
        #pragma unroll
        for (int kh = 0; kh < 3; ++kh) { if (!tap_in_set(ph, th, kh)) continue;
            #pragma unroll
            for (int kw = 0; kw < 3; ++kw) { if (!tap_in_set(pw, tw, kw)) continue;
                s += w1[((((b*3+kd)*3+kh)*3+kw)*Cin + ci)*Cmid + co]; } } }
    g_wcomb[idx] = s;
}

__global__ void pack_b1() {
    int idx = blockIdx.x * 256 + threadIdx.x;      // 4*8*64*1024 = 2,097,152
    int k   = idx & 1023;
    int co  = (idx >> 10) & 63;
    int par = (idx >> 16) & 7;
    int b   = idx >> 19;
    int tap = k >> 7, ci = k & 127;
    float v = g_wcomb[(((size_t)(b*8+par)*8 + tap)*128 + ci)*64 + co];
    uint16_t h, l; split1(v, h, l);
    size_t o = ((size_t)(b*8+par)*64 + co)*1024 + k;
    ((uint16_t*)g_B1h)[o] = h; ((uint16_t*)g_B1l)[o] = l;
}

__global__ void pack_b2(const float* __restrict__ w2) {
    int idx = blockIdx.x * 256 + threadIdx.x;      // 4*64*3456 = 884,736
    int k  = idx % 3456;
    int co = (idx / 3456) & 63;
    int b  = idx / (3456*64);
    int tap = k >> 7, ci = k & 127;
    float v = w2[(((size_t)b*27 + tap)*128 + ci)*64 + co];
    uint16_t h, l; split1(v, h, l);
    size_t o = ((size_t)b*64 + co)*3456 + k;
    ((uint16_t*)g_B2h)[o] = h; ((uint16_t*)g_B2l)[o] = l;
}

__global__ void split_kernel(const float* __restrict__ src, int n4, int mode) {
    int i = blockIdx.x * 256 + threadIdx.x;
    if (i >= n4) return;
    float4 v = ((const float4*)src)[i];
    uint2 H, L; split4(v, H, L);
    uint2* Hd = (uint2*)(mode ? g_skh : g_xh);
    uint2* Ld = (uint2*)(mode ? g_skl : g_xl);
    Hd[i] = H; Ld[i] = L;
}

__global__ void y1bn_split() {
    __shared__ float s[128];
    if (threadIdx.x < 128) s[threadIdx.x] = g_ss1[threadIdx.x];
    __syncthreads();
    int i = blockIdx.x * 256 + threadIdx.x;        // 4,194,304 float4s
    float4 v = ((const float4*)g_y1)[i];
    int cb = (i & 15) * 4;
    v.x = fmaxf(fmaf(v.x, s[cb+0], s[64+cb+0]), 0.f);
    v.y = fmaxf(fmaf(v.y, s[cb+1], s[64+cb+1]), 0.f);
    v.z = fmaxf(fmaf(v.z, s[cb+2], s[64+cb+2]), 0.f);
    v.w = fmaxf(fmaf(v.w, s[cb+3], s[64+cb+3]), 0.f);
    uint2 H, L; split4(v, H, L);
    ((uint2*)g_y1h)[i] = H; ((uint2*)g_y1l)[i] = L;
}

// ---------------- shared GEMM compute step: one 64-wide K chunk ----------------
// acc: float[2][4][4]; wm=warp m (0..3), wn=warp n (0..1), lid lane
__device__ __forceinline__ void chunk_compute(uint32_t sb, int buf, int wm, int wn, int lid,
                                              float acc[2][4][4]) {
    const uint32_t aH = sb + SA_H(buf), aL = sb + SA_L(buf);
    const uint32_t bH = sb + SB_H(buf), bL = sb + SB_L(buf);
    #pragma unroll
    for (int ks = 0; ks < 4; ++ks) {
        uint32_t ah[2][4], al[2][4], bh[4][2], bl[4][2];
        #pragma unroll
        for (int mt = 0; mt < 2; ++mt) {
            int row = wm*32 + mt*16 + (lid & 15);
            int col = ks*16 + (lid >> 4) * 8;
            uint32_t off = (uint32_t)(row*APITCH + col) * 2u;
            ldsm4(ah[mt], aH + off);
            ldsm4(al[mt], aL + off);
        }
        #pragma unroll
        for (int nt = 0; nt < 4; ++nt) {
            int row = wn*32 + nt*8 + (lid & 7);
            int col = ks*16 + ((lid >> 3) & 1) * 8;
            uint32_t off = (uint32_t)(row*APITCH + col) * 2u;
            ldsm2(bh[nt], bH + off);
            ldsm2(bl[nt], bL + off);
        }
        #pragma unroll
        for (int mt = 0; mt < 2; ++mt)
            #pragma unroll
            for (int nt = 0; nt < 4; ++nt) {
                mma16816(acc[mt][nt], ah[mt], bh[nt]);
                mma16816(acc[mt][nt], al[mt], bh[nt]);
                mma16816(acc[mt][nt], ah[mt], bl[nt]);
            }
    }
}

// store prefetched regs into buffer `buf`
__device__ __forceinline__ void chunk_store(uint32_t sb, int buf, int arow, int aseg,
                                            int brow, int bq,
                                            const uint4* paH, const uint4* paL,
                                            const uint4* pbH, const uint4* pbL) {
    #pragma unroll
    for (int j = 0; j < 4; ++j) {
        uint32_t off = (uint32_t)(arow*APITCH + aseg*32 + j*8) * 2u;
        sts16(sb + SA_H(buf) + off, paH[j]);
        sts16(sb + SA_L(buf) + off, paL[j]);
    }
    #pragma unroll
    for (int j = 0; j < 2; ++j) {
        uint32_t off = (uint32_t)(brow*APITCH + bq*16 + j*8) * 2u;
        sts16(sb + SB_H(buf) + off, pbH[j]);
        sts16(sb + SB_L(buf) + off, pbL[j]);
    }
}

// ---------------- conv1: warp-MMA GEMM, folded 2x2x2 conv ----------------
// per (b,par): M=8192, N=64, K = 16 chunks of 64 (8 taps x 2 ci-halves)
__global__ void __launch_bounds__(256, 1) conv1_mma() {
    extern __shared__ char smraw[];
    const uint32_t sb = smem_u32(smraw);
    const int b = blockIdx.z, par = blockIdx.y;
    const int pd = (par>>2)&1, phh = (par>>1)&1, pw = par&1;
    const int t = threadIdx.x, wid = t >> 5, lid = t & 31;
    const int wm = wid & 3, wn = wid >> 2;

    const int arow = t >> 1, aseg = t & 1;
    const int m  = blockIdx.x*128 + arow;
    const int mw = m & 31, mh = (m >> 5) & 31, md = m >> 10;
    const int brow = t >> 2, bq = t & 3;

    float acc[2][4][4];
    #pragma unroll
    for (int i = 0; i < 2; ++i)
        #pragma unroll
        for (int j = 0; j < 4; ++j)
            #pragma unroll
            for (int k = 0; k < 4; ++k) acc[i][j][k] = 0.f;

    uint4 paH[4], paL[4], pbH[2], pbL[2];
    const uint4 z4 = make_uint4(0,0,0,0);

#define C1_FETCH(NC) { \
    int tap = (NC) >> 1, cihalf = (NC) & 1; \
    int td = (tap>>2)&1, th = (tap>>1)&1, tw = tap&1; \
    int z = md + (pd ? td : td-1), y = mh + (phh ? th : th-1), xx = mw + (pw ? tw : tw-1); \
    bool valid = ((unsigned)z < 8u) && ((unsigned)y < 32u) && ((unsigned)xx < 32u); \
    size_t sp = ((size_t)(((b*8+z)*32+y)*32+xx))*128 + (size_t)cihalf*64; \
    const uint4* SH = (const uint4*)(g_xh + sp) + aseg*4; \
    const uint4* SL = (const uint4*)(g_xl + sp) + aseg*4; \
    _Pragma("unroll") for (int j = 0; j < 4; ++j) { \
        paH[j] = valid ? SH[j] : z4; paL[j] = valid ? SL[j] : z4; } \
    size_t base = ((size_t)(b*8+par)*64 + brow)*1024 + (size_t)(NC)*64; \
    const uint4* BH = (const uint4*)(g_B1h + base); \
    const uint4* BL = (const uint4*)(g_B1l + base); \
    _Pragma("unroll") for (int j = 0; j < 2; ++j) { \
        pbH[j] = BH[bq*2+j]; pbL[j] = BL[bq*2+j]; } \
}

    C1_FETCH(0);
    chunk_store(sb, 0, arow, aseg, brow, bq, paH, paL, pbH, pbL);
    __syncthreads();

    const int NC = 16;
    for (int ck = 0; ck < NC; ++ck) {
        if (ck + 1 < NC) { C1_FETCH(ck + 1); }
        chunk_compute(sb, ck & 1, wm, wn, lid, acc);
        if (ck + 1 < NC)
            chunk_store(sb, (ck+1) & 1, arow, aseg, brow, bq, paH, paL, pbH, pbL);
        __syncthreads();
    }
#undef C1_FETCH

    // epilogue: remap to fine coordinates, write fp32
    #pragma unroll
    for (int mt = 0; mt < 2; ++mt) {
        int r0 = wm*32 + mt*16 + (lid >> 2);
        #pragma unroll
        for (int half = 0; half < 2; ++half) {
            int mrow = blockIdx.x*128 + r0 + half*8;
            int ww = mrow & 31, hh = (mrow >> 5) & 31, dd = mrow >> 10;
            int od = 2*dd + pd, oh = 2*hh + phh, ow = 2*ww + pw;
            float* dst = g_y1 + ((size_t)(((b*16+od)*64+oh)*64+ow))*64 + wn*32 + (lid & 3)*2;
            #pragma unroll
            for (int nt = 0; nt < 4; ++nt) {
                float2 v = make_float2(acc[mt][nt][half*2+0], acc[mt][nt][half*2+1]);
                *(float2*)(dst + nt*8) = v;
            }
        }
    }
}

// ---------------- conv2: warp-MMA GEMM, 3x3x3 over concat(BN1+ReLU(y1), skip) ----------------
// per b: M=65536, N=64, K = 54 chunks of 64 (27 taps x 2 ci-halves)
__global__ void __launch_bounds__(256, 1) conv2_mma(const float* __restrict__ dummy,
                                                    float* __restrict__ out) {
    extern __shared__ char smraw[];
    const uint32_t sb = smem_u32(smraw);
    const int b = blockIdx.y;
    const int t = threadIdx.x, wid = t >> 5, lid = t & 31;
    const int wm = wid & 3, wn = wid >> 2;

    const int arow = t >> 1, aseg = t & 1;
    const int m   = blockIdx.x*128 + arow;
    const int ow_ = m & 63, oh_ = (m >> 6) & 63, od_ = m >> 12;
    const int brow = t >> 2, bq = t & 3;

    float acc[2][4][4];
    #pragma unroll
    for (int i = 0; i < 2; ++i)
        #pragma unroll
        for (int j = 0; j < 4; ++j)
            #pragma unroll
            for (int k = 0; k < 4; ++k) acc[i][j][k] = 0.f;

    uint4 paH[4], paL[4], pbH[2], pbL[2];
    const uint4 z4 = make_uint4(0,0,0,0);

#define C2_FETCH(NC) { \
    int tap = (NC) >> 1, cihalf = (NC) & 1; \
    int td = tap/9, r_ = tap%9, th = r_/3, tw = r_%3; \
    int z = od_ + td - 1, y = oh_ + th - 1, xx = ow_ + tw - 1; \
    bool valid = ((unsigned)z < 16u) && ((unsigned)y < 64u) && ((unsigned)xx < 64u); \
    size_t sp = ((size_t)(((b*16+z)*64+y)*64+xx))*64; \
    const __nv_bfloat16* Hs = cihalf ? g_skh : g_y1h; \
    const __nv_bfloat16* Ls = cihalf ? g_skl : g_y1l; \
    const uint4* SH = (const uint4*)(Hs + sp) + aseg*4; \
    const uint4* SL = (const uint4*)(Ls + sp) + aseg*4; \
    _Pragma("unroll") for (int j = 0; j < 4; ++j) { \
        paH[j] = valid ? SH[j] : z4; paL[j] = valid ? SL[j] : z4; } \
    size_t base = ((size_t)b*64 + brow)*3456 + (size_t)(NC)*64; \
    const uint4* BH = (const uint4*)(g_B2h + base); \
    const uint4* BL = (const uint4*)(g_B2l + base); \
    _Pragma("unroll") for (int j = 0; j < 2; ++j) { \
        pbH[j] = BH[bq*2+j]; pbL[j] = BL[bq*2+j]; } \
}

    C2_FETCH(0);
    chunk_store(sb, 0, arow, aseg, brow, bq, paH, paL, pbH, pbL);
    __syncthreads();

    const int NC = 54;
    for (int ck = 0; ck < NC; ++ck) {
        if (ck + 1 < NC) { C2_FETCH(ck + 1); }
        chunk_compute(sb, ck & 1, wm, wn, lid, acc);
        if (ck + 1 < NC)
            chunk_store(sb, (ck+1) & 1, arow, aseg, brow, bq, paH, paL, pbH, pbL);
        __syncthreads();
    }
#undef C2_FETCH

    #pragma unroll
    for (int mt = 0; mt < 2; ++mt) {
        int r0 = wm*32 + mt*16 + (lid >> 2);
        #pragma unroll
        for (int half = 0; half < 2; ++half) {
            int mrow = blockIdx.x*128 + r0 + half*8;
            float* dst = out + ((size_t)b*65536 + mrow)*64 + wn*32 + (lid & 3)*2;
            #pragma unroll
            for (int nt = 0; nt < 4; ++nt) {
                float2 v = make_float2(acc[mt][nt][half*2+0], acc[mt][nt][half*2+1]);
                *(float2*)(dst + nt*8) = v;
            }
        }
    }
    (void)dummy;
}

// ---------------- BN statistics ----------------
__global__ void stats_partial(const float* __restrict__ extsrc, int use_y1) {
    const float* src = use_y1 ? g_y1 : extsrc;
    const int c = threadIdx.x & 63;
    const int r = threadIdx.x >> 6;
    float s = 0.f, q = 0.f;
    for (int p = blockIdx.x*4 + r; p < NPOS; p += STATS_BLOCKS*4) {
        float v = src[(size_t)p*64 + c];
        s += v; q = fmaf(v, v, q);
    }
    __shared__ float shs[4][64], shq[4][64];
    shs[r][c] = s; shq[r][c] = q;
    __syncthreads();
    if (r == 0) {
        s = shs[0][c] + shs[1][c] + shs[2][c] + shs[3][c];
        q = shq[0][c] + shq[1][c] + shq[2][c] + shq[3][c];
        g_part[blockIdx.x*128 + c]      = s;
        g_part[blockIdx.x*128 + 64 + c] = q;
    }
}

__global__ void reduce_stats(const float* __restrict__ gamma,
                             const float* __restrict__ beta, int which) {
    const int c = threadIdx.x & 63;
    const int r = threadIdx.x >> 6;   // 0..7 with 512 threads
    float s = 0.f, q = 0.f;
    for (int i = r; i < STATS_BLOCKS; i += 8) {
        s += g_part[i*128 + c];
        q += g_part[i*128 + 64 + c];
    }
    __shared__ float shs[8][64], shq[8][64];
    shs[r][c] = s; shq[r][c] = q;
    __syncthreads();
    if (r == 0) {
        s = 0.f; q = 0.f;
        #pragma unroll
        for (int i = 0; i < 8; ++i) { s += shs[i][c]; q += shq[i][c]; }
        float mean = s * (1.f / (float)NPOS);
        float var  = q * (1.f / (float)NPOS) - mean*mean;
        float sc   = gamma[c] * rsqrtf(var + BN_EPS);
        float sh   = beta[c] - mean * sc;
        float* ss = which ? g_ss1 : g_ss2;
        ss[c] = sc; ss[64 + c] = sh;
    }
}

__global__ void bn_relu_kernel(float* __restrict__ out) {
    __shared__ float s[128];
    if (threadIdx.x < 128) s[threadIdx.x] = g_ss2[threadIdx.x];
    __syncthreads();
    size_t i = (size_t)blockIdx.x*256 + threadIdx.x;
    float4 v = ((float4*)out)[i];
    int cb = ((int)i & 15) * 4;
    v.x = fmaxf(fmaf(v.x, s[cb+0], s[64+cb+0]), 0.f);
    v.y = fmaxf(fmaf(v.y, s[cb+1], s[64+cb+1]), 0.f);
    v.z = fmaxf(fmaf(v.z, s[cb+2], s[64+cb+2]), 0.f);
    v.w = fmaxf(fmaf(v.w, s[cb+3], s[64+cb+3]), 0.f);
    ((float4*)out)[i] = v;
}

// ---------------- launcher ----------------
extern "C" void kernel_launch(void* const* d_in, const int* in_sizes, int n_in,
                              void* d_out, int out_size) {
    (void)in_sizes; (void)n_in; (void)out_size;
    const float* x      = (const float*)d_in[0];
    const float* w1     = (const float*)d_in[1];
    const float* w2     = (const float*)d_in[2];
    const float* skip   = (const float*)d_in[3];
    const float* gamma1 = (const float*)d_in[4];
    const float* beta1  = (const float*)d_in[5];
    const float* gamma2 = (const float*)d_in[6];
    const float* beta2  = (const float*)d_in[7];
    float* out = (float*)d_out;

    static int smem_set = 0;
    if (!smem_set) {
        cudaFuncSetAttribute(conv1_mma, cudaFuncAttributeMaxDynamicSharedMemorySize, SMEM_DYN);
        cudaFuncSetAttribute(conv2_mma, cudaFuncAttributeMaxDynamicSharedMemorySize, SMEM_DYN);
        smem_set = 1;
    }

    // weight prep + input splits
    build_wcomb<<<8192, 256>>>(w1);
    pack_b1<<<8192, 256>>>();
    pack_b2<<<3456, 256>>>(w2);
    split_kernel<<<4096, 256>>>(x, 1048576, 0);       // x fp32 -> bf16 hi/lo
    split_kernel<<<16384, 256>>>(skip, 4194304, 1);   // skip fp32 -> bf16 hi/lo

    // conv1 (warp MMA) -> g_y1 fp32
    conv1_mma<<<dim3(64, 8, B), 256, SMEM_DYN>>>();
    // BN1 stats
    stats_partial<<<STATS_BLOCKS, 256>>>(nullptr, 1);
    reduce_stats<<<1, 512>>>(gamma1, beta1, 1);
    // BN1 + ReLU + split -> bf16 hi/lo
    y1bn_split<<<16384, 256>>>();
    // conv2 (warp MMA) -> out fp32
    conv2_mma<<<dim3(512, B), 256, SMEM_DYN>>>(nullptr, out);
    // BN2 stats + apply
    stats_partial<<<STATS_BLOCKS, 256>>>(out, 0);
    reduce_stats<<<1, 512>>>(gamma2, beta2, 0);
    bn_relu_kernel<<<16384, 256>>>(out);
}

// round 5
// speedup vs baseline: 2.5097x; 1.1194x over previous
#include <cuda_runtime.h>
#include <cuda_bf16.h>
#include <cstdint>
#include <cstddef>

// ---------------- problem constants ----------------
#define B     4
#define Dc    8
#define Hc    32
#define Wc_   32
#define Cin   128
#define Cmid  64
#define Df    16
#define Hf    64
#define Wf    64
#define NPOS  (B*Df*Hf*Wf)
#define BN_EPS 1e-3f
#define NPART 2048            // per-CTA stat partials (both convs launch 2048 CTAs)

// ---------------- device scratch ----------------
__device__ float g_y1[(size_t)NPOS*Cmid];              // raw conv1 output (fp32)
__device__ float g_wcomb[B*8*8*Cin*Cmid];              // folded conv1 weights (fp32)
__device__ float g_part[NPART*128];                    // per-CTA (sum[64], sumsq[64])
__device__ float g_ss1[128];                           // BN1 scale[64],shift[64]
__device__ float g_ss2[128];

__device__ __align__(16) __nv_bfloat16 g_xh[B*Dc*Hc*Wc_*Cin];
__device__ __align__(16) __nv_bfloat16 g_xl[B*Dc*Hc*Wc_*Cin];
__device__ __align__(16) __nv_bfloat16 g_skh[(size_t)NPOS*Cmid];
__device__ __align__(16) __nv_bfloat16 g_skl[(size_t)NPOS*Cmid];
__device__ __align__(16) __nv_bfloat16 g_y1h[(size_t)NPOS*Cmid];
__device__ __align__(16) __nv_bfloat16 g_y1l[(size_t)NPOS*Cmid];
__device__ __align__(16) __nv_bfloat16 g_B1h[B*8*Cmid*1024];   // [b][par][co][k]
__device__ __align__(16) __nv_bfloat16 g_B1l[B*8*Cmid*1024];
__device__ __align__(16) __nv_bfloat16 g_B2h[B*Cmid*3456];     // [b][co][k]
__device__ __align__(16) __nv_bfloat16 g_B2l[B*Cmid*3456];

// ---------------- PTX helpers (baseline ISA; compiles for plain sm_103) -----
__device__ __forceinline__ uint32_t smem_u32(const void* p) {
    uint32_t a;
    asm("{ .reg .u64 t; cvta.to.shared.u64 t, %1; cvt.u32.u64 %0, t; }" : "=r"(a) : "l"(p));
    return a;
}
__device__ __forceinline__ void ldsm4(uint32_t* r, uint32_t addr) {
    asm volatile("ldmatrix.sync.aligned.m8n8.x4.shared.b16 {%0,%1,%2,%3}, [%4];"
                 : "=r"(r[0]), "=r"(r[1]), "=r"(r[2]), "=r"(r[3]) : "r"(addr));
}
__device__ __forceinline__ void ldsm2(uint32_t* r, uint32_t addr) {
    asm volatile("ldmatrix.sync.aligned.m8n8.x2.shared.b16 {%0,%1}, [%2];"
                 : "=r"(r[0]), "=r"(r[1]) : "r"(addr));
}
__device__ __forceinline__ void mma16816(float* c, const uint32_t* a, const uint32_t* b) {
    asm volatile("mma.sync.aligned.m16n8k16.row.col.f32.bf16.bf16.f32 "
                 "{%0,%1,%2,%3}, {%4,%5,%6,%7}, {%8,%9}, {%0,%1,%2,%3};"
                 : "+f"(c[0]), "+f"(c[1]), "+f"(c[2]), "+f"(c[3])
                 : "r"(a[0]), "r"(a[1]), "r"(a[2]), "r"(a[3]), "r"(b[0]), "r"(b[1]));
}
__device__ __forceinline__ void cp16(uint32_t dst, const void* src, uint32_t srcsize) {
    asm volatile("cp.async.cg.shared.global [%0], [%1], 16, %2;"
                 :: "r"(dst), "l"(src), "r"(srcsize) : "memory");
}
#define CP_COMMIT()  asm volatile("cp.async.commit_group;" ::: "memory")
#define CP_WAIT(n)   asm volatile("cp.async.wait_group %0;" :: "n"(n) : "memory")

// ---------------- SMEM layout: XOR-swizzled tiles, 96KB total ----------------
// A tile: 128 rows x 128B (64 bf16); B tile: 64 rows x 128B. granule = 16B,
// swizzled column: gcol' = gcol ^ (row & 7)
#define SA_H(bf) ((bf)*49152u)
#define SA_L(bf) ((bf)*49152u + 16384u)
#define SB_H(bf) ((bf)*49152u + 32768u)
#define SB_L(bf) ((bf)*49152u + 40960u)
#define SMEM_DYN 98304

// ---------------- fp32 -> bf16 hi/lo split helpers ----------------
__device__ __forceinline__ void split1(float v, uint16_t& h, uint16_t& l) {
    __nv_bfloat16 hb = __float2bfloat16(v);
    __nv_bfloat16 lb = __float2bfloat16(v - __bfloat162float(hb));
    h = __bfloat16_as_ushort(hb); l = __bfloat16_as_ushort(lb);
}
__device__ __forceinline__ void split4(float4 v, uint2& H, uint2& L) {
    uint16_t h0,h1,h2,h3,l0,l1,l2,l3;
    split1(v.x,h0,l0); split1(v.y,h1,l1); split1(v.z,h2,l2); split1(v.w,h3,l3);
    H.x = (uint32_t)h0 | ((uint32_t)h1 << 16); H.y = (uint32_t)h2 | ((uint32_t)h3 << 16);
    L.x = (uint32_t)l0 | ((uint32_t)l1 << 16); L.y = (uint32_t)l2 | ((uint32_t)l3 << 16);
}

// ---------------- conv1 weight folding ----------------
__device__ __forceinline__ bool tap_in_set(int p, int t, int k) {
    return p ? (t ? (k == 2) : (k <= 1)) : (t ? (k >= 1) : (k == 0));
}
__global__ void build_wcomb(const float* __restrict__ w1) {
    int idx = blockIdx.x * 256 + threadIdx.x;
    int co  = idx & 63;
    int ci  = (idx >> 6) & 127;
    int tap = (idx >> 13) & 7;
    int par = (idx >> 16) & 7;
    int b   = idx >> 19;
    int td = (tap >> 2) & 1, th = (tap >> 1) & 1, tw = tap & 1;
    int pd = (par >> 2) & 1, ph = (par >> 1) & 1, pw = par & 1;
    float s = 0.f;
    #pragma unroll
    for (int kd = 0; kd < 3; ++kd) { if (!tap_in_set(pd, td, kd)) continue;
        #pragma unroll
        for (int kh = 0; kh < 3; ++kh) { if (!tap_in_set(ph, th, kh)) continue;
            #pragma unroll
            for (int kw = 0; kw < 3; ++kw) { if (!tap_in_set(pw, tw, kw)) continue;
                s += w1[((((b*3+kd)*3+kh)*3+kw)*Cin + ci)*Cmid + co]; } } }
    g_wcomb[idx] = s;
}

__global__ void pack_b1() {
    int idx = blockIdx.x * 256 + threadIdx.x;      // 2,097,152
    int k   = idx & 1023;
    int co  = (idx >> 10) & 63;
    int par = (idx >> 16) & 7;
    int b   = idx >> 19;
    int tap = k >> 7, ci = k & 127;
    float v = g_wcomb[(((size_t)(b*8+par)*8 + tap)*128 + ci)*64 + co];
    uint16_t h, l; split1(v, h, l);
    size_t o = ((size_t)(b*8+par)*64 + co)*1024 + k;
    ((uint16_t*)g_B1h)[o] = h; ((uint16_t*)g_B1l)[o] = l;
}

__global__ void pack_b2(const float* __restrict__ w2) {
    int idx = blockIdx.x * 256 + threadIdx.x;      // 884,736
    int k  = idx % 3456;
    int co = (idx / 3456) & 63;
    int b  = idx / (3456*64);
    int tap = k >> 7, ci = k & 127;
    float v = w2[(((size_t)b*27 + tap)*128 + ci)*64 + co];
    uint16_t h, l; split1(v, h, l);
    size_t o = ((size_t)b*64 + co)*3456 + k;
    ((uint16_t*)g_B2h)[o] = h; ((uint16_t*)g_B2l)[o] = l;
}

__global__ void split_kernel(const float* __restrict__ src, int n4, int mode) {
    int i = blockIdx.x * 256 + threadIdx.x;
    if (i >= n4) return;
    float4 v = ((const float4*)src)[i];
    uint2 H, L; split4(v, H, L);
    uint2* Hd = (uint2*)(mode ? g_skh : g_xh);
    uint2* Ld = (uint2*)(mode ? g_skl : g_xl);
    Hd[i] = H; Ld[i] = L;
}

__global__ void y1bn_split() {
    __shared__ float s[128];
    if (threadIdx.x < 128) s[threadIdx.x] = g_ss1[threadIdx.x];
    __syncthreads();
    int i = blockIdx.x * 256 + threadIdx.x;
    float4 v = ((const float4*)g_y1)[i];
    int cb = (i & 15) * 4;
    v.x = fmaxf(fmaf(v.x, s[cb+0], s[64+cb+0]), 0.f);
    v.y = fmaxf(fmaf(v.y, s[cb+1], s[64+cb+1]), 0.f);
    v.z = fmaxf(fmaf(v.z, s[cb+2], s[64+cb+2]), 0.f);
    v.w = fmaxf(fmaf(v.w, s[cb+3], s[64+cb+3]), 0.f);
    uint2 H, L; split4(v, H, L);
    ((uint2*)g_y1h)[i] = H; ((uint2*)g_y1l)[i] = L;
}

// ---------------- shared GEMM compute step: one 64-wide K chunk ----------------
__device__ __forceinline__ void chunk_compute(uint32_t sb, int buf, int wm, int wn, int lid,
                                              float acc[2][4][4]) {
    const uint32_t aH = sb + SA_H(buf), aL = sb + SA_L(buf);
    const uint32_t bH = sb + SB_H(buf), bL = sb + SB_L(buf);
    #pragma unroll
    for (int ks = 0; ks < 4; ++ks) {
        uint32_t ah[2][4], al[2][4], bh[4][2], bl[4][2];
        #pragma unroll
        for (int mt = 0; mt < 2; ++mt) {
            int row = wm*32 + mt*16 + (lid & 15);
            uint32_t g = (uint32_t)(ks*2 + (lid >> 4));
            uint32_t off = (uint32_t)row*128u + ((g ^ ((uint32_t)row & 7u))*16u);
            ldsm4(ah[mt], aH + off);
            ldsm4(al[mt], aL + off);
        }
        #pragma unroll
        for (int nt = 0; nt < 4; ++nt) {
            int row = wn*32 + nt*8 + (lid & 7);
            uint32_t g = (uint32_t)(ks*2 + ((lid >> 3) & 1));
            uint32_t off = (uint32_t)row*128u + ((g ^ ((uint32_t)row & 7u))*16u);
            ldsm2(bh[nt], bH + off);
            ldsm2(bl[nt], bL + off);
        }
        #pragma unroll
        for (int mt = 0; mt < 2; ++mt)
            #pragma unroll
            for (int nt = 0; nt < 4; ++nt) {
                mma16816(acc[mt][nt], ah[mt], bh[nt]);
                mma16816(acc[mt][nt], al[mt], bh[nt]);
                mma16816(acc[mt][nt], ah[mt], bl[nt]);
            }
    }
}

// ---------------- fused per-CTA BN stats from accumulators ----------------
// deterministic: shfl-bfly within warp, fixed-order smem reduce across warps
__device__ __forceinline__ void epilogue_stats(char* smraw, int cta,
                                               int wid, int lid, int t,
                                               const float acc[2][4][4]) {
    float scol[8], qcol[8];
    #pragma unroll
    for (int i = 0; i < 8; ++i) { scol[i] = 0.f; qcol[i] = 0.f; }
    #pragma unroll
    for (int mt = 0; mt < 2; ++mt)
        #pragma unroll
        for (int nt = 0; nt < 4; ++nt) {
            float v0 = acc[mt][nt][0], v1 = acc[mt][nt][1];
            float v2 = acc[mt][nt][2], v3 = acc[mt][nt][3];
            scol[nt*2+0] += v0 + v2; qcol[nt*2+0] += v0*v0 + v2*v2;
            scol[nt*2+1] += v1 + v3; qcol[nt*2+1] += v1*v1 + v3*v3;
        }
    #pragma unroll
    for (int m = 4; m < 32; m <<= 1)
        #pragma unroll
        for (int i = 0; i < 8; ++i) {
            scol[i] += __shfl_xor_sync(0xffffffffu, scol[i], m);
            qcol[i] += __shfl_xor_sync(0xffffffffu, qcol[i], m);
        }
    float* sts = (float*)smraw;   // [0..255]=sums [8 warps][32 cols], [256..511]=sumsq
    if (lid < 4) {
        #pragma unroll
        for (int i = 0; i < 8; ++i) {
            int col32 = (i >> 1)*8 + lid*2 + (i & 1);
            sts[wid*32 + col32]       = scol[i];
            sts[256 + wid*32 + col32] = qcol[i];
        }
    }
    __syncthreads();
    if (t < 128) {
        int c = t & 63, isq = t >> 6;
        int wnn = c >> 5, c32 = c & 31;
        float v = 0.f;
        #pragma unroll
        for (int m = 0; m < 4; ++m)
            v += sts[isq*256 + (wnn*4 + m)*32 + c32];
        g_part[(size_t)cta*128 + isq*64 + c] = v;
    }
}

// ---------------- conv1: warp-MMA GEMM, folded 2x2x2 conv ----------------
__global__ void __launch_bounds__(256, 2) conv1_mma() {
    extern __shared__ char smraw[];
    const uint32_t sb = smem_u32(smraw);
    const int b = blockIdx.z, par = blockIdx.y;
    const int pd = (par>>2)&1, phh = (par>>1)&1, pw = par&1;
    const int t = threadIdx.x, wid = t >> 5, lid = t & 31;
    const int wm = wid & 3, wn = wid >> 2;

    const int arow = t >> 1, aseg = t & 1;
    const int m  = blockIdx.x*128 + arow;
    const int mw = m & 31, mh = (m >> 5) & 31, md = m >> 10;
    const int brow = t >> 2;

    float acc[2][4][4];
    #pragma unroll
    for (int i = 0; i < 2; ++i)
        #pragma unroll
        for (int j = 0; j < 4; ++j)
            #pragma unroll
            for (int k = 0; k < 4; ++k) acc[i][j][k] = 0.f;

#define C1_ISSUE(CK, BUF) { \
    int tap = (CK) >> 1, cihalf = (CK) & 1; \
    int td = (tap>>2)&1, th = (tap>>1)&1, tw = tap&1; \
    int z = md + (pd ? td : td-1), y = mh + (phh ? th : th-1), xx = mw + (pw ? tw : tw-1); \
    bool valid = ((unsigned)z < 8u) && ((unsigned)y < 32u) && ((unsigned)xx < 32u); \
    size_t sp = valid ? (((size_t)(((b*8+z)*32+y)*32+xx))*128 + (size_t)cihalf*64) : 0; \
    uint32_t szA = valid ? 16u : 0u; \
    _Pragma("unroll") for (int j = 0; j < 4; ++j) { \
        uint32_t g = (uint32_t)(aseg*4 + j); \
        uint32_t dsto = (uint32_t)arow*128u + ((g ^ ((uint32_t)arow & 7u))*16u); \
        cp16(sb + SA_H(BUF) + dsto, g_xh + sp + g*8, szA); \
        cp16(sb + SA_L(BUF) + dsto, g_xl + sp + g*8, szA); } \
    size_t wb = ((size_t)(b*8+par)*64 + brow)*1024 + (size_t)(CK)*64; \
    _Pragma("unroll") for (int j = 0; j < 2; ++j) { \
        uint32_t gc = (uint32_t)(((t*2 + j) & 7)); \
        uint32_t dsto = (uint32_t)brow*128u + ((gc ^ ((uint32_t)brow & 7u))*16u); \
        cp16(sb + SB_H(BUF) + dsto, g_B1h + wb + gc*8, 16u); \
        cp16(sb + SB_L(BUF) + dsto, g_B1l + wb + gc*8, 16u); } \
    CP_COMMIT(); \
}

    const int NC = 16;
    C1_ISSUE(0, 0);
    C1_ISSUE(1, 1);
    for (int ck = 0; ck < NC; ++ck) {
        if (ck < NC-1) { CP_WAIT(1); } else { CP_WAIT(0); }
        __syncthreads();
        chunk_compute(sb, ck & 1, wm, wn, lid, acc);
        __syncthreads();
        if (ck + 2 < NC) { C1_ISSUE(ck + 2, ck & 1); }
    }
#undef C1_ISSUE

    // epilogue: remap to fine coordinates, write fp32
    #pragma unroll
    for (int mt = 0; mt < 2; ++mt) {
        int r0 = wm*32 + mt*16 + (lid >> 2);
        #pragma unroll
        for (int half = 0; half < 2; ++half) {
            int mrow = blockIdx.x*128 + r0 + half*8;
            int ww = mrow & 31, hh = (mrow >> 5) & 31, dd = mrow >> 10;
            int od = 2*dd + pd, oh = 2*hh + phh, ow = 2*ww + pw;
            float* dst = g_y1 + ((size_t)(((b*16+od)*64+oh)*64+ow))*64 + wn*32 + (lid & 3)*2;
            #pragma unroll
            for (int nt = 0; nt < 4; ++nt) {
                float2 v = make_float2(acc[mt][nt][half*2+0], acc[mt][nt][half*2+1]);
                *(float2*)(dst + nt*8) = v;
            }
        }
    }
    int cta = (blockIdx.z*8 + blockIdx.y)*64 + blockIdx.x;
    epilogue_stats(smraw, cta, wid, lid, t, acc);
}

// ---------------- conv2: warp-MMA GEMM, 3x3x3 over concat(BN1+ReLU(y1), skip) ----
__global__ void __launch_bounds__(256, 2) conv2_mma(float* __restrict__ out) {
    extern __shared__ char smraw[];
    const uint32_t sb = smem_u32(smraw);
    const int b = blockIdx.y;
    const int t = threadIdx.x, wid = t >> 5, lid = t & 31;
    const int wm = wid & 3, wn = wid >> 2;

    const int arow = t >> 1, aseg = t & 1;
    const int m   = blockIdx.x*128 + arow;
    const int ow_ = m & 63, oh_ = (m >> 6) & 63, od_ = m >> 12;
    const int brow = t >> 2;

    float acc[2][4][4];
    #pragma unroll
    for (int i = 0; i < 2; ++i)
        #pragma unroll
        for (int j = 0; j < 4; ++j)
            #pragma unroll
            for (int k = 0; k < 4; ++k) acc[i][j][k] = 0.f;

#define C2_ISSUE(CK, BUF) { \
    int tap = (CK) >> 1, cihalf = (CK) & 1; \
    int td = tap/9, r_ = tap%9, th = r_/3, tw = r_%3; \
    int z = od_ + td - 1, y = oh_ + th - 1, xx = ow_ + tw - 1; \
    bool valid = ((unsigned)z < 16u) && ((unsigned)y < 64u) && ((unsigned)xx < 64u); \
    size_t sp = valid ? (((size_t)(((b*16+z)*64+y)*64+xx))*64) : 0; \
    uint32_t szA = valid ? 16u : 0u; \
    const __nv_bfloat16* Hs = cihalf ? g_skh : g_y1h; \
    const __nv_bfloat16* Ls = cihalf ? g_skl : g_y1l; \
    _Pragma("unroll") for (int j = 0; j < 4; ++j) { \
        uint32_t g = (uint32_t)(aseg*4 + j); \
        uint32_t dsto = (uint32_t)arow*128u + ((g ^ ((uint32_t)arow & 7u))*16u); \
        cp16(sb + SA_H(BUF) + dsto, Hs + sp + g*8, szA); \
        cp16(sb + SA_L(BUF) + dsto, Ls + sp + g*8, szA); } \
    size_t wb = ((size_t)b*64 + brow)*3456 + (size_t)(CK)*64; \
    _Pragma("unroll") for (int j = 0; j < 2; ++j) { \
        uint32_t gc = (uint32_t)(((t*2 + j) & 7)); \
        uint32_t dsto = (uint32_t)brow*128u + ((gc ^ ((uint32_t)brow & 7u))*16u); \
        cp16(sb + SB_H(BUF) + dsto, g_B2h + wb + gc*8, 16u); \
        cp16(sb + SB_L(BUF) + dsto, g_B2l + wb + gc*8, 16u); } \
    CP_COMMIT(); \
}

    const int NC = 54;
    C2_ISSUE(0, 0);
    C2_ISSUE(1, 1);
    for (int ck = 0; ck < NC; ++ck) {
        if (ck < NC-1) { CP_WAIT(1); } else { CP_WAIT(0); }
        __syncthreads();
        chunk_compute(sb, ck & 1, wm, wn, lid, acc);
        __syncthreads();
        if (ck + 2 < NC) { C2_ISSUE(ck + 2, ck & 1); }
    }
#undef C2_ISSUE

    #pragma unroll
    for (int mt = 0; mt < 2; ++mt) {
        int r0 = wm*32 + mt*16 + (lid >> 2);
        #pragma unroll
        for (int half = 0; half < 2; ++half) {
            int mrow = blockIdx.x*128 + r0 + half*8;
            float* dst = out + ((size_t)b*65536 + mrow)*64 + wn*32 + (lid & 3)*2;
            #pragma unroll
            for (int nt = 0; nt < 4; ++nt) {
                float2 v = make_float2(acc[mt][nt][half*2+0], acc[mt][nt][half*2+1]);
                *(float2*)(dst + nt*8) = v;
            }
        }
    }
    int cta = blockIdx.y*512 + blockIdx.x;
    epilogue_stats(smraw, cta, wid, lid, t, acc);
}

// ---------------- stats reduction (deterministic) ----------------
__global__ void reduce_stats(const float* __restrict__ gamma,
                             const float* __restrict__ beta, int which) {
    const int c = threadIdx.x & 63;
    const int r = threadIdx.x >> 6;   // 0..7 (512 threads)
    float s = 0.f, q = 0.f;
    for (int i = r; i < NPART; i += 8) {
        s += g_part[(size_t)i*128 + c];
        q += g_part[(size_t)i*128 + 64 + c];
    }
    __shared__ float shs[8][64], shq[8][64];
    shs[r][c] = s; shq[r][c] = q;
    __syncthreads();
    if (r == 0) {
        s = 0.f; q = 0.f;
        #pragma unroll
        for (int i = 0; i < 8; ++i) { s += shs[i][c]; q += shq[i][c]; }
        float mean = s * (1.f / (float)NPOS);
        float var  = q * (1.f / (float)NPOS) - mean*mean;
        float sc   = gamma[c] * rsqrtf(var + BN_EPS);
        float sh   = beta[c] - mean * sc;
        float* ss = which ? g_ss1 : g_ss2;
        ss[c] = sc; ss[64 + c] = sh;
    }
}

__global__ void bn_relu_kernel(float* __restrict__ out) {
    __shared__ float s[128];
    if (threadIdx.x < 128) s[threadIdx.x] = g_ss2[threadIdx.x];
    __syncthreads();
    size_t i = (size_t)blockIdx.x*256 + threadIdx.x;
    float4 v = ((float4*)out)[i];
    int cb = ((int)i & 15) * 4;
    v.x = fmaxf(fmaf(v.x, s[cb+0], s[64+cb+0]), 0.f);
    v.y = fmaxf(fmaf(v.y, s[cb+1], s[64+cb+1]), 0.f);
    v.z = fmaxf(fmaf(v.z, s[cb+2], s[64+cb+2]), 0.f);
    v.w = fmaxf(fmaf(v.w, s[cb+3], s[64+cb+3]), 0.f);
    ((float4*)out)[i] = v;
}

// ---------------- launcher ----------------
extern "C" void kernel_launch(void* const* d_in, const int* in_sizes, int n_in,
                              void* d_out, int out_size) {
    (void)in_sizes; (void)n_in; (void)out_size;
    const float* x      = (const float*)d_in[0];
    const float* w1     = (const float*)d_in[1];
    const float* w2     = (const float*)d_in[2];
    const float* skip   = (const float*)d_in[3];
    const float* gamma1 = (const float*)d_in[4];
    const float* beta1  = (const float*)d_in[5];
    const float* gamma2 = (const float*)d_in[6];
    const float* beta2  = (const float*)d_in[7];
    float* out = (float*)d_out;

    cudaFuncSetAttribute(conv1_mma, cudaFuncAttributeMaxDynamicSharedMemorySize, SMEM_DYN);
    cudaFuncSetAttribute(conv2_mma, cudaFuncAttributeMaxDynamicSharedMemorySize, SMEM_DYN);

    // weight prep + input splits
    build_wcomb<<<8192, 256>>>(w1);
    pack_b1<<<8192, 256>>>();
    pack_b2<<<3456, 256>>>(w2);
    split_kernel<<<4096, 256>>>(x, 1048576, 0);
    split_kernel<<<16384, 256>>>(skip, 4194304, 1);

    // conv1 (warp MMA, fused BN1 partials) -> g_y1 + g_part
    conv1_mma<<<dim3(64, 8, B), 256, SMEM_DYN>>>();
    reduce_stats<<<1, 512>>>(gamma1, beta1, 1);
    // BN1 + ReLU + split -> bf16 hi/lo
    y1bn_split<<<16384, 256>>>();
    // conv2 (warp MMA, fused BN2 partials) -> out + g_part
    conv2_mma<<<dim3(512, B), 256, SMEM_DYN>>>(out);
    reduce_stats<<<1, 512>>>(gamma2, beta2, 0);
    bn_relu_kernel<<<16384, 256>>>(out);
}

// round 6
// speedup vs baseline: 3.5322x; 1.4074x over previous
#include <cuda_runtime.h>
#include <cuda_fp16.h>
#include <cstdint>
#include <cstddef>

// ---------------- problem constants ----------------
#define B     4
#define Dc    8
#define Hc    32
#define Wc_   32
#define Cin   128
#define Cmid  64
#define Df    16
#define Hf    64
#define Wf    64
#define NPOS  (B*Df*Hf*Wf)
#define BN_EPS 1e-3f
#define NPART 2048            // per-CTA stat partials (both convs launch 2048 CTAs)

// ---------------- device scratch ----------------
__device__ float g_y1[(size_t)NPOS*Cmid];              // raw conv1 output (fp32)
__device__ float g_wcomb[B*8*8*Cin*Cmid];              // folded conv1 weights (fp32)
__device__ float g_part[NPART*128];                    // per-CTA (sum[64], sumsq[64])
__device__ float g_ss1[128];                           // BN1 scale[64],shift[64]
__device__ float g_ss2[128];

// A-side: single fp16. B-side: fp16 hi/lo split (~22-bit weights).
__device__ __align__(16) uint16_t g_xa[B*Dc*Hc*Wc_*Cin];
__device__ __align__(16) uint16_t g_ska[(size_t)NPOS*Cmid];
__device__ __align__(16) uint16_t g_y1a[(size_t)NPOS*Cmid];
__device__ __align__(16) uint16_t g_B1h[B*8*Cmid*1024];   // [b][par][co][k]
__device__ __align__(16) uint16_t g_B1l[B*8*Cmid*1024];
__device__ __align__(16) uint16_t g_B2h[B*Cmid*3456];     // [b][co][k]
__device__ __align__(16) uint16_t g_B2l[B*Cmid*3456];

// ---------------- PTX helpers (baseline ISA; compiles for plain sm_103) -----
__device__ __forceinline__ uint32_t smem_u32(const void* p) {
    uint32_t a;
    asm("{ .reg .u64 t; cvta.to.shared.u64 t, %1; cvt.u32.u64 %0, t; }" : "=r"(a) : "l"(p));
    return a;
}
__device__ __forceinline__ void ldsm4(uint32_t* r, uint32_t addr) {
    asm volatile("ldmatrix.sync.aligned.m8n8.x4.shared.b16 {%0,%1,%2,%3}, [%4];"
                 : "=r"(r[0]), "=r"(r[1]), "=r"(r[2]), "=r"(r[3]) : "r"(addr));
}
__device__ __forceinline__ void ldsm2(uint32_t* r, uint32_t addr) {
    asm volatile("ldmatrix.sync.aligned.m8n8.x2.shared.b16 {%0,%1}, [%2];"
                 : "=r"(r[0]), "=r"(r[1]) : "r"(addr));
}
__device__ __forceinline__ void mma16816h(float* c, const uint32_t* a, const uint32_t* b) {
    asm volatile("mma.sync.aligned.m16n8k16.row.col.f32.f16.f16.f32 "
                 "{%0,%1,%2,%3}, {%4,%5,%6,%7}, {%8,%9}, {%0,%1,%2,%3};"
                 : "+f"(c[0]), "+f"(c[1]), "+f"(c[2]), "+f"(c[3])
                 : "r"(a[0]), "r"(a[1]), "r"(a[2]), "r"(a[3]), "r"(b[0]), "r"(b[1]));
}
__device__ __forceinline__ void cp16(uint32_t dst, const void* src, uint32_t srcsize) {
    asm volatile("cp.async.cg.shared.global [%0], [%1], 16, %2;"
                 :: "r"(dst), "l"(src), "r"(srcsize) : "memory");
}
#define CP_COMMIT()  asm volatile("cp.async.commit_group;" ::: "memory")
#define CP_WAIT(n)   asm volatile("cp.async.wait_group %0;" :: "n"(n) : "memory")

// ---------------- SMEM layout: XOR-swizzled tiles, 64KB total ----------------
// A tile: 128 rows x 128B (64 fp16); B tiles: 64 rows x 128B each.
// granule = 16B, swizzled column: gcol' = gcol ^ (row & 7)
#define SA(bf)   ((bf)*32768u)
#define SB_H(bf) ((bf)*32768u + 16384u)
#define SB_L(bf) ((bf)*32768u + 24576u)
#define SMEM_DYN 65536

// ---------------- fp16 helpers ----------------
__device__ __forceinline__ uint32_t pack2h(float a, float b) {
    return (uint32_t)__half_as_ushort(__float2half_rn(a)) |
           ((uint32_t)__half_as_ushort(__float2half_rn(b)) << 16);
}
__device__ __forceinline__ void splitB(float v, uint16_t& h, uint16_t& l) {
    __half hb = __float2half_rn(v);
    __half lb = __float2half_rn(v - __half2float(hb));
    h = __half_as_ushort(hb); l = __half_as_ushort(lb);
}

// ---------------- conv1 weight folding ----------------
__device__ __forceinline__ bool tap_in_set(int p, int t, int k) {
    return p ? (t ? (k == 2) : (k <= 1)) : (t ? (k >= 1) : (k == 0));
}
__global__ void build_wcomb(const float* __restrict__ w1) {
    int idx = blockIdx.x * 256 + threadIdx.x;
    int co  = idx & 63;
    int ci  = (idx >> 6) & 127;
    int tap = (idx >> 13) & 7;
    int par = (idx >> 16) & 7;
    int b   = idx >> 19;
    int td = (tap >> 2) & 1, th = (tap >> 1) & 1, tw = tap & 1;
    int pd = (par >> 2) & 1, ph = (par >> 1) & 1, pw = par & 1;
    float s = 0.f;
    #pragma unroll
    for (int kd = 0; kd < 3; ++kd) { if (!tap_in_set(pd, td, kd)) continue;
        #pragma unroll
        for (int kh = 0; kh < 3; ++kh) { if (!tap_in_set(ph, th, kh)) continue;
            #pragma unroll
            for (int kw = 0; kw < 3; ++kw) { if (!tap_in_set(pw, tw, kw)) continue;
                s += w1[((((b*3+kd)*3+kh)*3+kw)*Cin + ci)*Cmid + co]; } } }
    g_wcomb[idx] = s;
}

__global__ void pack_b1() {
    int idx = blockIdx.x * 256 + threadIdx.x;      // 2,097,152
    int k   = idx & 1023;
    int co  = (idx >> 10) & 63;
    int par = (idx >> 16) & 7;
    int b   = idx >> 19;
    int tap = k >> 7, ci = k & 127;
    float v = g_wcomb[(((size_t)(b*8+par)*8 + tap)*128 + ci)*64 + co];
    uint16_t h, l; splitB(v, h, l);
    size_t o = ((size_t)(b*8+par)*64 + co)*1024 + k;
    g_B1h[o] = h; g_B1l[o] = l;
}

__global__ void pack_b2(const float* __restrict__ w2) {
    int idx = blockIdx.x * 256 + threadIdx.x;      // 884,736
    int k  = idx % 3456;
    int co = (idx / 3456) & 63;
    int b  = idx / (3456*64);
    int tap = k >> 7, ci = k & 127;
    float v = w2[(((size_t)b*27 + tap)*128 + ci)*64 + co];
    uint16_t h, l; splitB(v, h, l);
    size_t o = ((size_t)b*64 + co)*3456 + k;
    g_B2h[o] = h; g_B2l[o] = l;
}

// fp32 -> fp16 conversion (A-side arrays)
__global__ void cvt_kernel(const float* __restrict__ src, int n4, int mode) {
    int i = blockIdx.x * 256 + threadIdx.x;
    if (i >= n4) return;
    float4 v = ((const float4*)src)[i];
    uint2 o = make_uint2(pack2h(v.x, v.y), pack2h(v.z, v.w));
    uint2* dst = (uint2*)(mode ? g_ska : g_xa);
    dst[i] = o;
}

// BN1 + ReLU + fp16 convert
__global__ void y1bn_cvt() {
    __shared__ float s[128];
    if (threadIdx.x < 128) s[threadIdx.x] = g_ss1[threadIdx.x];
    __syncthreads();
    int i = blockIdx.x * 256 + threadIdx.x;        // 4,194,304 float4s
    float4 v = ((const float4*)g_y1)[i];
    int cb = (i & 15) * 4;
    v.x = fmaxf(fmaf(v.x, s[cb+0], s[64+cb+0]), 0.f);
    v.y = fmaxf(fmaf(v.y, s[cb+1], s[64+cb+1]), 0.f);
    v.z = fmaxf(fmaf(v.z, s[cb+2], s[64+cb+2]), 0.f);
    v.w = fmaxf(fmaf(v.w, s[cb+3], s[64+cb+3]), 0.f);
    ((uint2*)g_y1a)[i] = make_uint2(pack2h(v.x, v.y), pack2h(v.z, v.w));
}

// ---------------- shared GEMM compute step: one 64-wide K chunk ----------------
// D += A(fp16) * (Bhi + Blo): 2 MMA terms per (mt,nt)
__device__ __forceinline__ void chunk_compute(uint32_t sb, int buf, int wm, int wn, int lid,
                                              float acc[2][4][4]) {
    const uint32_t aT = sb + SA(buf);
    const uint32_t bH = sb + SB_H(buf), bL = sb + SB_L(buf);
    #pragma unroll
    for (int ks = 0; ks < 4; ++ks) {
        uint32_t ah[2][4], bh[4][2], bl[4][2];
        #pragma unroll
        for (int mt = 0; mt < 2; ++mt) {
            int row = wm*32 + mt*16 + (lid & 15);
            uint32_t g = (uint32_t)(ks*2 + (lid >> 4));
            uint32_t off = (uint32_t)row*128u + ((g ^ ((uint32_t)row & 7u))*16u);
            ldsm4(ah[mt], aT + off);
        }
        #pragma unroll
        for (int nt = 0; nt < 4; ++nt) {
            int row = wn*32 + nt*8 + (lid & 7);
            uint32_t g = (uint32_t)(ks*2 + ((lid >> 3) & 1));
            uint32_t off = (uint32_t)row*128u + ((g ^ ((uint32_t)row & 7u))*16u);
            ldsm2(bh[nt], bH + off);
            ldsm2(bl[nt], bL + off);
        }
        #pragma unroll
        for (int mt = 0; mt < 2; ++mt)
            #pragma unroll
            for (int nt = 0; nt < 4; ++nt) {
                mma16816h(acc[mt][nt], ah[mt], bh[nt]);
                mma16816h(acc[mt][nt], ah[mt], bl[nt]);
            }
    }
}

// ---------------- fused per-CTA BN stats from accumulators ----------------
__device__ __forceinline__ void epilogue_stats(char* smraw, int cta,
                                               int wid, int lid, int t,
                                               const float acc[2][4][4]) {
    float scol[8], qcol[8];
    #pragma unroll
    for (int i = 0; i < 8; ++i) { scol[i] = 0.f; qcol[i] = 0.f; }
    #pragma unroll
    for (int mt = 0; mt < 2; ++mt)
        #pragma unroll
        for (int nt = 0; nt < 4; ++nt) {
            float v0 = acc[mt][nt][0], v1 = acc[mt][nt][1];
            float v2 = acc[mt][nt][2], v3 = acc[mt][nt][3];
            scol[nt*2+0] += v0 + v2; qcol[nt*2+0] += v0*v0 + v2*v2;
            scol[nt*2+1] += v1 + v3; qcol[nt*2+1] += v1*v1 + v3*v3;
        }
    #pragma unroll
    for (int m = 4; m < 32; m <<= 1)
        #pragma unroll
        for (int i = 0; i < 8; ++i) {
            scol[i] += __shfl_xor_sync(0xffffffffu, scol[i], m);
            qcol[i] += __shfl_xor_sync(0xffffffffu, qcol[i], m);
        }
    float* sts = (float*)smraw;
    if (lid < 4) {
        #pragma unroll
        for (int i = 0; i < 8; ++i) {
            int col32 = (i >> 1)*8 + lid*2 + (i & 1);
            sts[wid*32 + col32]       = scol[i];
            sts[256 + wid*32 + col32] = qcol[i];
        }
    }
    __syncthreads();
    if (t < 128) {
        int c = t & 63, isq = t >> 6;
        int wnn = c >> 5, c32 = c & 31;
        float v = 0.f;
        #pragma unroll
        for (int m = 0; m < 4; ++m)
            v += sts[isq*256 + (wnn*4 + m)*32 + c32];
        g_part[(size_t)cta*128 + isq*64 + c] = v;
    }
}

// ---------------- conv1: warp-MMA GEMM, folded 2x2x2 conv ----------------
__global__ void __launch_bounds__(256, 2) conv1_mma() {
    extern __shared__ char smraw[];
    const uint32_t sb = smem_u32(smraw);
    const int b = blockIdx.z, par = blockIdx.y;
    const int pd = (par>>2)&1, phh = (par>>1)&1, pw = par&1;
    const int t = threadIdx.x, wid = t >> 5, lid = t & 31;
    const int wm = wid & 3, wn = wid >> 2;

    const int arow = t >> 1, aseg = t & 1;
    const int m  = blockIdx.x*128 + arow;
    const int mw = m & 31, mh = (m >> 5) & 31, md = m >> 10;
    const int brow = t >> 2;

    float acc[2][4][4];
    #pragma unroll
    for (int i = 0; i < 2; ++i)
        #pragma unroll
        for (int j = 0; j < 4; ++j)
            #pragma unroll
            for (int k = 0; k < 4; ++k) acc[i][j][k] = 0.f;

#define C1_ISSUE(CK, BUF) { \
    int tap = (CK) >> 1, cihalf = (CK) & 1; \
    int td = (tap>>2)&1, th = (tap>>1)&1, tw = tap&1; \
    int z = md + (pd ? td : td-1), y = mh + (phh ? th : th-1), xx = mw + (pw ? tw : tw-1); \
    bool valid = ((unsigned)z < 8u) && ((unsigned)y < 32u) && ((unsigned)xx < 32u); \
    size_t sp = valid ? (((size_t)(((b*8+z)*32+y)*32+xx))*128 + (size_t)cihalf*64) : 0; \
    uint32_t szA = valid ? 16u : 0u; \
    _Pragma("unroll") for (int j = 0; j < 4; ++j) { \
        uint32_t g = (uint32_t)(aseg*4 + j); \
        uint32_t dsto = (uint32_t)arow*128u + ((g ^ ((uint32_t)arow & 7u))*16u); \
        cp16(sb + SA(BUF) + dsto, g_xa + sp + g*8, szA); } \
    size_t wb = ((size_t)(b*8+par)*64 + brow)*1024 + (size_t)(CK)*64; \
    _Pragma("unroll") for (int j = 0; j < 2; ++j) { \
        uint32_t gc = (uint32_t)(((t*2 + j) & 7)); \
        uint32_t dsto = (uint32_t)brow*128u + ((gc ^ ((uint32_t)brow & 7u))*16u); \
        cp16(sb + SB_H(BUF) + dsto, g_B1h + wb + gc*8, 16u); \
        cp16(sb + SB_L(BUF) + dsto, g_B1l + wb + gc*8, 16u); } \
    CP_COMMIT(); \
}

    const int NC = 16;
    C1_ISSUE(0, 0);
    C1_ISSUE(1, 1);
    for (int ck = 0; ck < NC; ++ck) {
        if (ck < NC-1) { CP_WAIT(1); } else { CP_WAIT(0); }
        __syncthreads();
        chunk_compute(sb, ck & 1, wm, wn, lid, acc);
        __syncthreads();
        if (ck + 2 < NC) { C1_ISSUE(ck + 2, ck & 1); }
    }
#undef C1_ISSUE

    // epilogue: remap to fine coordinates, write fp32
    #pragma unroll
    for (int mt = 0; mt < 2; ++mt) {
        int r0 = wm*32 + mt*16 + (lid >> 2);
        #pragma unroll
        for (int half = 0; half < 2; ++half) {
            int mrow = blockIdx.x*128 + r0 + half*8;
            int ww = mrow & 31, hh = (mrow >> 5) & 31, dd = mrow >> 10;
            int od = 2*dd + pd, oh = 2*hh + phh, ow = 2*ww + pw;
            float* dst = g_y1 + ((size_t)(((b*16+od)*64+oh)*64+ow))*64 + wn*32 + (lid & 3)*2;
            #pragma unroll
            for (int nt = 0; nt < 4; ++nt) {
                float2 v = make_float2(acc[mt][nt][half*2+0], acc[mt][nt][half*2+1]);
                *(float2*)(dst + nt*8) = v;
            }
        }
    }
    int cta = (blockIdx.z*8 + blockIdx.y)*64 + blockIdx.x;
    epilogue_stats(smraw, cta, wid, lid, t, acc);
}

// ---------------- conv2: warp-MMA GEMM, 3x3x3 over concat(BN1+ReLU(y1), skip) ----
__global__ void __launch_bounds__(256, 2) conv2_mma(float* __restrict__ out) {
    extern __shared__ char smraw[];
    const uint32_t sb = smem_u32(smraw);
    const int b = blockIdx.y;
    const int t = threadIdx.x, wid = t >> 5, lid = t & 31;
    const int wm = wid & 3, wn = wid >> 2;

    const int arow = t >> 1, aseg = t & 1;
    const int m   = blockIdx.x*128 + arow;
    const int ow_ = m & 63, oh_ = (m >> 6) & 63, od_ = m >> 12;
    const int brow = t >> 2;

    float acc[2][4][4];
    #pragma unroll
    for (int i = 0; i < 2; ++i)
        #pragma unroll
        for (int j = 0; j < 4; ++j)
            #pragma unroll
            for (int k = 0; k < 4; ++k) acc[i][j][k] = 0.f;

#define C2_ISSUE(CK, BUF) { \
    int tap = (CK) >> 1, cihalf = (CK) & 1; \
    int td = tap/9, r_ = tap%9, th = r_/3, tw = r_%3; \
    int z = od_ + td - 1, y = oh_ + th - 1, xx = ow_ + tw - 1; \
    bool valid = ((unsigned)z < 16u) && ((unsigned)y < 64u) && ((unsigned)xx < 64u); \
    size_t sp = valid ? (((size_t)(((b*16+z)*64+y)*64+xx))*64) : 0; \
    uint32_t szA = valid ? 16u : 0u; \
    const uint16_t* As_ = cihalf ? g_ska : g_y1a; \
    _Pragma("unroll") for (int j = 0; j < 4; ++j) { \
        uint32_t g = (uint32_t)(aseg*4 + j); \
        uint32_t dsto = (uint32_t)arow*128u + ((g ^ ((uint32_t)arow & 7u))*16u); \
        cp16(sb + SA(BUF) + dsto, As_ + sp + g*8, szA); } \
    size_t wb = ((size_t)b*64 + brow)*3456 + (size_t)(CK)*64; \
    _Pragma("unroll") for (int j = 0; j < 2; ++j) { \
        uint32_t gc = (uint32_t)(((t*2 + j) & 7)); \
        uint32_t dsto = (uint32_t)brow*128u + ((gc ^ ((uint32_t)brow & 7u))*16u); \
        cp16(sb + SB_H(BUF) + dsto, g_B2h + wb + gc*8, 16u); \
        cp16(sb + SB_L(BUF) + dsto, g_B2l + wb + gc*8, 16u); } \
    CP_COMMIT(); \
}

    const int NC = 54;
    C2_ISSUE(0, 0);
    C2_ISSUE(1, 1);
    for (int ck = 0; ck < NC; ++ck) {
        if (ck < NC-1) { CP_WAIT(1); } else { CP_WAIT(0); }
        __syncthreads();
        chunk_compute(sb, ck & 1, wm, wn, lid, acc);
        __syncthreads();
        if (ck + 2 < NC) { C2_ISSUE(ck + 2, ck & 1); }
    }
#undef C2_ISSUE

    #pragma unroll
    for (int mt = 0; mt < 2; ++mt) {
        int r0 = wm*32 + mt*16 + (lid >> 2);
        #pragma unroll
        for (int half = 0; half < 2; ++half) {
            int mrow = blockIdx.x*128 + r0 + half*8;
            float* dst = out + ((size_t)b*65536 + mrow)*64 + wn*32 + (lid & 3)*2;
            #pragma unroll
            for (int nt = 0; nt < 4; ++nt) {
                float2 v = make_float2(acc[mt][nt][half*2+0], acc[mt][nt][half*2+1]);
                *(float2*)(dst + nt*8) = v;
            }
        }
    }
    int cta = blockIdx.y*512 + blockIdx.x;
    epilogue_stats(smraw, cta, wid, lid, t, acc);
}

// ---------------- stats reduction (deterministic) ----------------
__global__ void reduce_stats(const float* __restrict__ gamma,
                             const float* __restrict__ beta, int which) {
    const int c = threadIdx.x & 63;
    const int r = threadIdx.x >> 6;   // 0..7 (512 threads)
    float s = 0.f, q = 0.f;
    for (int i = r; i < NPART; i += 8) {
        s += g_part[(size_t)i*128 + c];
        q += g_part[(size_t)i*128 + 64 + c];
    }
    __shared__ float shs[8][64], shq[8][64];
    shs[r][c] = s; shq[r][c] = q;
    __syncthreads();
    if (r == 0) {
        s = 0.f; q = 0.f;
        #pragma unroll
        for (int i = 0; i < 8; ++i) { s += shs[i][c]; q += shq[i][c]; }
        float mean = s * (1.f / (float)NPOS);
        float var  = q * (1.f / (float)NPOS) - mean*mean;
        float sc   = gamma[c] * rsqrtf(var + BN_EPS);
        float sh   = beta[c] - mean * sc;
        float* ss = which ? g_ss1 : g_ss2;
        ss[c] = sc; ss[64 + c] = sh;
    }
}

__global__ void bn_relu_kernel(float* __restrict__ out) {
    __shared__ float s[128];
    if (threadIdx.x < 128) s[threadIdx.x] = g_ss2[threadIdx.x];
    __syncthreads();
    size_t i = (size_t)blockIdx.x*256 + threadIdx.x;
    float4 v = ((float4*)out)[i];
    int cb = ((int)i & 15) * 4;
    v.x = fmaxf(fmaf(v.x, s[cb+0], s[64+cb+0]), 0.f);
    v.y = fmaxf(fmaf(v.y, s[cb+1], s[64+cb+1]), 0.f);
    v.z = fmaxf(fmaf(v.z, s[cb+2], s[64+cb+2]), 0.f);
    v.w = fmaxf(fmaf(v.w, s[cb+3], s[64+cb+3]), 0.f);
    ((float4*)out)[i] = v;
}

// ---------------- launcher ----------------
extern "C" void kernel_launch(void* const* d_in, const int* in_sizes, int n_in,
                              void* d_out, int out_size) {
    (void)in_sizes; (void)n_in; (void)out_size;
    const float* x      = (const float*)d_in[0];
    const float* w1     = (const float*)d_in[1];
    const float* w2     = (const float*)d_in[2];
    const float* skip   = (const float*)d_in[3];
    const float* gamma1 = (const float*)d_in[4];
    const float* beta1  = (const float*)d_in[5];
    const float* gamma2 = (const float*)d_in[6];
    const float* beta2  = (const float*)d_in[7];
    float* out = (float*)d_out;

    cudaFuncSetAttribute(conv1_mma, cudaFuncAttributeMaxDynamicSharedMemorySize, SMEM_DYN);
    cudaFuncSetAttribute(conv2_mma, cudaFuncAttributeMaxDynamicSharedMemorySize, SMEM_DYN);

    // weight prep + input conversion
    build_wcomb<<<8192, 256>>>(w1);
    pack_b1<<<8192, 256>>>();
    pack_b2<<<3456, 256>>>(w2);
    cvt_kernel<<<4096, 256>>>(x, 1048576, 0);
    cvt_kernel<<<16384, 256>>>(skip, 4194304, 1);

    // conv1 (warp MMA, fused BN1 partials) -> g_y1 + g_part
    conv1_mma<<<dim3(64, 8, B), 256, SMEM_DYN>>>();
    reduce_stats<<<1, 512>>>(gamma1, beta1, 1);
    // BN1 + ReLU + fp16 convert
    y1bn_cvt<<<16384, 256>>>();
    // conv2 (warp MMA, fused BN2 partials) -> out + g_part
    conv2_mma<<<dim3(512, B), 256, SMEM_DYN>>>(out);
    reduce_stats<<<1, 512>>>(gamma2, beta2, 0);
    bn_relu_kernel<<<16384, 256>>>(out);
}